// round 10
// baseline (speedup 1.0000x reference)
#include <cuda_runtime.h>

#define B_  128
#define T_  512
#define H_  512
#define L_  256
#define HB_ (B_ * H_)   // one h buffer (65536 words)

__device__ float    g_ig[(size_t)T_ * B_ * 3 * H_];
__device__ unsigned g_h[2 * HB_];        // step-parity double buffer (tf32 words)
__device__ float    g_hx[HB_];           // exact fp32 h_final for k_out
__device__ unsigned long long g_flag[128 * 16];

__device__ __forceinline__ unsigned f2tf(float f) {
    unsigned u;
    asm("cvt.rna.tf32.f32 %0, %1;" : "=r"(u) : "f"(f));
    return u;
}
__device__ __forceinline__ void mma8(float c[4],
                                     unsigned a0, unsigned a1, unsigned a2, unsigned a3,
                                     unsigned b0, unsigned b1) {
    asm volatile(
        "mma.sync.aligned.m16n8k8.row.col.f32.tf32.tf32.f32 "
        "{%0,%1,%2,%3}, {%4,%5,%6,%7}, {%8,%9}, {%0,%1,%2,%3};"
        : "+f"(c[0]), "+f"(c[1]), "+f"(c[2]), "+f"(c[3])
        : "r"(a0), "r"(a1), "r"(a2), "r"(a3), "r"(b0), "r"(b1));
}
__device__ __forceinline__ float sigf(float x) { return 1.0f / (1.0f + __expf(-x)); }
__device__ __forceinline__ void red_release(unsigned long long* p) {
    asm volatile("red.add.release.gpu.global.u64 [%0], 1;" :: "l"(p) : "memory");
}
__device__ __forceinline__ unsigned long long ld_acquire(const unsigned long long* p) {
    unsigned long long v;
    asm volatile("ld.acquire.gpu.u64 %0, [%1];" : "=l"(v) : "l"(p) : "memory");
    return v;
}

__global__ void k_zero() {
    for (int i = threadIdx.x; i < 128 * 16; i += 256) g_flag[i] = 0ULL;
}

// ===========================================================================
// Kernel 1: IG = X@Wih^T + b  (FROZEN round-5 config: 857us known-good)
// ===========================================================================
__global__ void __launch_bounds__(256) k_igemm(const float* __restrict__ x,
                                               const float* __restrict__ Wih,
                                               const float* __restrict__ bias) {
    __shared__ unsigned As[128][20];
    __shared__ unsigned Bs[128][20];

    const int t   = blockIdx.y;
    const int n0  = blockIdx.x * 128;
    const int tid = threadIdx.x;
    const int w    = tid >> 5;
    const int lane = tid & 31;
    const int gid  = lane >> 2;
    const int tig  = lane & 3;
    const int mrow = (w >> 2) * 64;
    const int ncol = (w & 3) * 32;

    float acc[4][4][4];
    #pragma unroll
    for (int i = 0; i < 4; i++)
        #pragma unroll
        for (int j = 0; j < 4; j++)
            #pragma unroll
            for (int q = 0; q < 4; q++) acc[i][j][q] = 0.0f;

    for (int k0 = 0; k0 < 512; k0 += 16) {
        #pragma unroll
        for (int it = 0; it < 2; it++) {
            int i  = tid + it * 256;
            int r  = i >> 2;
            int c4 = (i & 3) * 4;
            float4 v = *(const float4*)(x + ((size_t)r * 512 + t) * 512 + k0 + c4);
            As[r][c4 + 0] = f2tf(v.x);
            As[r][c4 + 1] = f2tf(v.y);
            As[r][c4 + 2] = f2tf(v.z);
            As[r][c4 + 3] = f2tf(v.w);
        }
        #pragma unroll
        for (int it = 0; it < 2; it++) {
            int i  = tid + it * 256;
            int r  = i >> 2;
            int c4 = (i & 3) * 4;
            float4 v = *(const float4*)(Wih + (size_t)(n0 + r) * 512 + k0 + c4);
            Bs[r][c4 + 0] = f2tf(v.x);
            Bs[r][c4 + 1] = f2tf(v.y);
            Bs[r][c4 + 2] = f2tf(v.z);
            Bs[r][c4 + 3] = f2tf(v.w);
        }
        __syncthreads();

        #pragma unroll
        for (int ks = 0; ks < 2; ks++) {
            const int kb = ks * 8;
            unsigned a[4][4];
            #pragma unroll
            for (int mt = 0; mt < 4; mt++) {
                int r = mrow + mt * 16 + gid;
                a[mt][0] = As[r][kb + tig];
                a[mt][1] = As[r + 8][kb + tig];
                a[mt][2] = As[r][kb + tig + 4];
                a[mt][3] = As[r + 8][kb + tig + 4];
            }
            #pragma unroll
            for (int nt = 0; nt < 4; nt++) {
                int n = ncol + nt * 8 + gid;
                unsigned b0 = Bs[n][kb + tig];
                unsigned b1 = Bs[n][kb + tig + 4];
                #pragma unroll
                for (int mt = 0; mt < 4; mt++)
                    mma8(acc[mt][nt], a[mt][0], a[mt][1], a[mt][2], a[mt][3], b0, b1);
            }
        }
        __syncthreads();
    }

    #pragma unroll
    for (int mt = 0; mt < 4; mt++) {
        #pragma unroll
        for (int nt = 0; nt < 4; nt++) {
            int r0 = mrow + mt * 16 + gid;
            int c0 = n0 + ncol + nt * 8 + 2 * tig;
            float bv0 = __ldg(bias + c0);
            float bv1 = __ldg(bias + c0 + 1);
            size_t base0 = ((size_t)t * 128 + r0) * 1536 + c0;
            size_t base1 = ((size_t)t * 128 + r0 + 8) * 1536 + c0;
            *(float2*)&g_ig[base0] = make_float2(acc[mt][nt][0] + bv0, acc[mt][nt][1] + bv1);
            *(float2*)&g_ig[base1] = make_float2(acc[mt][nt][2] + bv0, acc[mt][nt][3] + bv1);
        }
    }
}

// ===========================================================================
// Kernel 2: persistent GRU recurrence — chunked producer pipeline,
//   double-buffered g_h (step parity) + double-buffered Sg, 1 BAR/step.
// ===========================================================================
#define WS_PITCH 516
#define SG_PITCH 52
#define SG_WORDS (8 * 32 * SG_PITCH)
#define SMEM_K2_WORDS (80 * WS_PITCH + SG_WORDS)
#define SMEM_K2_BYTES (SMEM_K2_WORDS * 4)

__global__ void __launch_bounds__(256, 1) k_rec(const float* __restrict__ Whh,
                                                const float* __restrict__ bn) {
    extern __shared__ unsigned smem[];
    unsigned* Ws  = smem;                          // [48][516] init only
    unsigned* Hs  = smem + 48 * WS_PITCH;          // [32][516] tf32 h
    float*    SgA = (float*)smem;                  // aliases Ws
    float*    SgB = (float*)(smem + 80 * WS_PITCH);

    const int tid  = threadIdx.x;
    const int lane = tid & 31;
    const int w    = tid >> 5;
    const int gid  = lane >> 2;
    const int tig  = lane & 3;
    const int mg   = blockIdx.x >> 5;
    const int cg   = blockIdx.x & 31;
    const int rowbase = mg * 32;
    const int colbase = cg * 16;

    for (int i = tid; i < 48 * 128; i += 256) {
        int lr   = i >> 7;
        int c4   = (i & 127) * 4;
        int grow = (lr >> 4) * 512 + colbase + (lr & 15);
        float4 v = *(const float4*)(Whh + (size_t)grow * 512 + c4);
        uint4 u = make_uint4(f2tf(v.x), f2tf(v.y), f2tf(v.z), f2tf(v.w));
        *(uint4*)&Ws[lr * WS_PITCH + c4] = u;
    }
    for (int i = tid; i < 32 * WS_PITCH; i += 256) Hs[i] = 0u;
    __syncthreads();

    const int kbase = w * 64;
    unsigned wf[8][6][2];
    #pragma unroll
    for (int kt = 0; kt < 8; kt++)
        #pragma unroll
        for (int nt = 0; nt < 6; nt++) {
            int base = (nt * 8 + gid) * WS_PITCH + kbase + kt * 8 + tig;
            wf[kt][nt][0] = Ws[base];
            wf[kt][nt][1] = Ws[base + 4];
        }
    __syncthreads();   // Ws free -> SgA

    const int bb = tid >> 3;
    const int jj = (tid * 2) & 15;
    const float bn0 = __ldg(bn + colbase + jj);
    const float bn1 = __ldg(bn + colbase + jj + 1);
    float2 hp = make_float2(0.0f, 0.0f);

    unsigned long long* myflag = &g_flag[(mg * 32 + cg) * 16];
    const unsigned long long* pf0 = &g_flag[(mg * 32 + w * 4) * 16];

    for (int t = 0; t < T_; t++) {
        const float* igb = g_ig + ((size_t)t * 128 + rowbase + bb) * 1536 + colbase + jj;
        float2 igr = __ldg((const float2*)(igb));
        float2 igz = __ldg((const float2*)(igb + 512));
        float2 ign = __ldg((const float2*)(igb + 1024));

        float c[2][6][4];
        #pragma unroll
        for (int m = 0; m < 2; m++)
            #pragma unroll
            for (int n = 0; n < 6; n++)
                #pragma unroll
                for (int q = 0; q < 4; q++) c[m][n][q] = 0.0f;

        if (t > 0) {
            const unsigned* hsrcbuf = g_h + (size_t)((t - 1) & 1) * HB_;
            // 4 producer chunks: poll -> restage 32x16 -> 2 kt of MMA
            #pragma unroll
            for (int p = 0; p < 4; p++) {
                if (lane == 0) {
                    const unsigned long long tgt = 256ULL * (unsigned long long)t;
                    while (ld_acquire(pf0 + p * 16) < tgt) { }
                }
                __syncwarp();
                const int pcol = kbase + p * 16;
                {
                    const unsigned* src = hsrcbuf + (rowbase + lane) * 512 + pcol;
                    #pragma unroll
                    for (int q = 0; q < 4; q++) {
                        uint4 v;
                        asm volatile("ld.global.cg.v4.u32 {%0,%1,%2,%3}, [%4];"
                                     : "=r"(v.x), "=r"(v.y), "=r"(v.z), "=r"(v.w)
                                     : "l"(src + q * 4));
                        *(uint4*)&Hs[lane * WS_PITCH + pcol + q * 4] = v;
                    }
                }
                __syncwarp();
                #pragma unroll
                for (int kk = 0; kk < 2; kk++) {
                    const int kt = p * 2 + kk;
                    const int kb = kbase + kt * 8;
                    unsigned a[2][4];
                    #pragma unroll
                    for (int m = 0; m < 2; m++) {
                        int r = m * 16 + gid;
                        a[m][0] = Hs[r * WS_PITCH + kb + tig];
                        a[m][1] = Hs[(r + 8) * WS_PITCH + kb + tig];
                        a[m][2] = Hs[r * WS_PITCH + kb + tig + 4];
                        a[m][3] = Hs[(r + 8) * WS_PITCH + kb + tig + 4];
                    }
                    #pragma unroll
                    for (int n = 0; n < 6; n++) {
                        mma8(c[0][n], a[0][0], a[0][1], a[0][2], a[0][3],
                             wf[kt][n][0], wf[kt][n][1]);
                        mma8(c[1][n], a[1][0], a[1][1], a[1][2], a[1][3],
                             wf[kt][n][0], wf[kt][n][1]);
                    }
                }
            }
        }
        // t==0: h0=0 -> partials stay 0 (skip MMA)

        float* Sgt = (t & 1) ? SgB : SgA;
        float* Sgw = Sgt + w * 32 * SG_PITCH;
        #pragma unroll
        for (int m = 0; m < 2; m++) {
            int r0 = m * 16 + gid, r1 = r0 + 8;
            #pragma unroll
            for (int n = 0; n < 6; n++) {
                int cb = n * 8 + 2 * tig;
                *(float2*)&Sgw[r0 * SG_PITCH + cb] = make_float2(c[m][n][0], c[m][n][1]);
                *(float2*)&Sgw[r1 * SG_PITCH + cb] = make_float2(c[m][n][2], c[m][n][3]);
            }
        }
        __syncthreads();   // single barrier per step

        {
            float hr0 = 0.f, hr1 = 0.f, hz0 = 0.f, hz1 = 0.f, hn0 = 0.f, hn1 = 0.f;
            #pragma unroll
            for (int k = 0; k < 8; k++) {
                const float* s = Sgt + k * 32 * SG_PITCH + bb * SG_PITCH;
                float2 vr = *(const float2*)(s + jj);
                float2 vz = *(const float2*)(s + 16 + jj);
                float2 vn = *(const float2*)(s + 32 + jj);
                hr0 += vr.x; hr1 += vr.y;
                hz0 += vz.x; hz1 += vz.y;
                hn0 += vn.x; hn1 += vn.y;
            }
            float r0 = sigf(igr.x + hr0);
            float r1 = sigf(igr.y + hr1);
            float z0 = sigf(igz.x + hz0);
            float z1 = sigf(igz.y + hz1);
            float n0 = tanhf(ign.x + r0 * (hn0 + bn0));
            float n1 = tanhf(ign.y + r1 * (hn1 + bn1));
            float h0 = (1.0f - z0) * n0 + z0 * hp.x;
            float h1 = (1.0f - z1) * n1 + z1 * hp.y;
            hp = make_float2(h0, h1);

            if (t < T_ - 1) {
                uint2 uv = make_uint2(f2tf(h0), f2tf(h1));
                unsigned* dst = g_h + (size_t)(t & 1) * HB_
                                + (rowbase + bb) * 512 + colbase + jj;
                asm volatile("st.global.cg.v2.u32 [%0], {%1,%2};"
                             :: "l"(dst), "r"(uv.x), "r"(uv.y) : "memory");
                red_release(myflag);   // per-lane: releases THIS lane's stores
            } else {
                *(float2*)(g_hx + (rowbase + bb) * 512 + colbase + jj) =
                    make_float2(h0, h1);
            }
        }
    }
}

// ===========================================================================
// Kernel 3: out = h_final @ Wlin^T + blin; warp-per-(b,32n), coalesced.
// ===========================================================================
__global__ void __launch_bounds__(256) k_out(const float* __restrict__ Wlin,
                                             const float* __restrict__ blin,
                                             float* __restrict__ out) {
    const int wg   = blockIdx.x * 8 + (threadIdx.x >> 5);
    const int lane = threadIdx.x & 31;
    const int b    = wg >> 4;
    const int nb   = (wg & 15) * 32;

    float4 h4[4];
    #pragma unroll
    for (int q = 0; q < 4; q++)
        h4[q] = *(const float4*)(g_hx + b * 512 + q * 128 + lane * 4);

    #pragma unroll 4
    for (int i = 0; i < 32; i++) {
        int n = nb + i;
        const float* wr = Wlin + (size_t)n * 512;
        float s = 0.0f;
        #pragma unroll
        for (int q = 0; q < 4; q++) {
            float4 wv = __ldg((const float4*)(wr + q * 128 + lane * 4));
            s += h4[q].x * wv.x + h4[q].y * wv.y + h4[q].z * wv.z + h4[q].w * wv.w;
        }
        s += __shfl_xor_sync(0xFFFFFFFF, s, 16);
        s += __shfl_xor_sync(0xFFFFFFFF, s, 8);
        s += __shfl_xor_sync(0xFFFFFFFF, s, 4);
        s += __shfl_xor_sync(0xFFFFFFFF, s, 2);
        s += __shfl_xor_sync(0xFFFFFFFF, s, 1);
        if (lane == 0) {
            float v = s + __ldg(blin + n);
            if (n < L_) out[b * L_ + n] = v;
            else        out[(size_t)B_ * L_ + b * L_ + (n - L_)] = v;
        }
    }
}

// ===========================================================================
extern "C" void kernel_launch(void* const* d_in, const int* in_sizes, int n_in,
                              void* d_out, int out_size) {
    const float* x    = (const float*)d_in[0];
    const float* Wih  = (const float*)d_in[1];
    const float* Whh  = (const float*)d_in[2];
    const float* b    = (const float*)d_in[3];
    const float* bn   = (const float*)d_in[4];
    const float* Wlin = (const float*)d_in[5];
    const float* blin = (const float*)d_in[6];
    float* out = (float*)d_out;

    cudaFuncSetAttribute(k_rec, cudaFuncAttributeMaxDynamicSharedMemorySize,
                         SMEM_K2_BYTES);

    dim3 g1(12, 512);
    k_igemm<<<g1, 256>>>(x, Wih, b);
    k_zero<<<1, 256>>>();
    k_rec<<<128, 256, SMEM_K2_BYTES>>>(Whh, bn);
    k_out<<<256, 256>>>(Wlin, blin, out);
}

// round 11
// speedup vs baseline: 1.6056x; 1.6056x over previous
#include <cuda_runtime.h>

#define B_  128
#define T_  512
#define H_  512
#define L_  256
#define HB_ (B_ * H_)

__device__ float    g_ig[(size_t)T_ * B_ * 3 * H_];
__device__ unsigned g_h[2 * HB_];        // step-parity double buffer (tf32 words)
__device__ float    g_hx[HB_];           // exact fp32 h_final
__device__ unsigned long long g_flag[128 * 16];

__device__ __forceinline__ unsigned f2tf(float f) {
    unsigned u;
    asm("cvt.rna.tf32.f32 %0, %1;" : "=r"(u) : "f"(f));
    return u;
}
__device__ __forceinline__ void mma8(float c[4],
                                     unsigned a0, unsigned a1, unsigned a2, unsigned a3,
                                     unsigned b0, unsigned b1) {
    asm volatile(
        "mma.sync.aligned.m16n8k8.row.col.f32.tf32.tf32.f32 "
        "{%0,%1,%2,%3}, {%4,%5,%6,%7}, {%8,%9}, {%0,%1,%2,%3};"
        : "+f"(c[0]), "+f"(c[1]), "+f"(c[2]), "+f"(c[3])
        : "r"(a0), "r"(a1), "r"(a2), "r"(a3), "r"(b0), "r"(b1));
}
__device__ __forceinline__ float sigf(float x) { return 1.0f / (1.0f + __expf(-x)); }
__device__ __forceinline__ unsigned long long arrive_release(unsigned long long* p) {
    unsigned long long old;
    asm volatile("atom.add.release.gpu.u64 %0, [%1], 1;" : "=l"(old) : "l"(p) : "memory");
    return old;
}
__device__ __forceinline__ unsigned long long ld_acquire(const unsigned long long* p) {
    unsigned long long v;
    asm volatile("ld.acquire.gpu.u64 %0, [%1];" : "=l"(v) : "l"(p) : "memory");
    return v;
}

__global__ void k_zero() {
    for (int i = threadIdx.x; i < 128 * 16; i += 256) g_flag[i] = 0ULL;
}

// ===========================================================================
// Kernel 1: IG = X@Wih^T + b  (FROZEN round-5 config: 857us known-good)
// ===========================================================================
__global__ void __launch_bounds__(256) k_igemm(const float* __restrict__ x,
                                               const float* __restrict__ Wih,
                                               const float* __restrict__ bias) {
    __shared__ unsigned As[128][20];
    __shared__ unsigned Bs[128][20];

    const int t   = blockIdx.y;
    const int n0  = blockIdx.x * 128;
    const int tid = threadIdx.x;
    const int w    = tid >> 5;
    const int lane = tid & 31;
    const int gid  = lane >> 2;
    const int tig  = lane & 3;
    const int mrow = (w >> 2) * 64;
    const int ncol = (w & 3) * 32;

    float acc[4][4][4];
    #pragma unroll
    for (int i = 0; i < 4; i++)
        #pragma unroll
        for (int j = 0; j < 4; j++)
            #pragma unroll
            for (int q = 0; q < 4; q++) acc[i][j][q] = 0.0f;

    for (int k0 = 0; k0 < 512; k0 += 16) {
        #pragma unroll
        for (int it = 0; it < 2; it++) {
            int i  = tid + it * 256;
            int r  = i >> 2;
            int c4 = (i & 3) * 4;
            float4 v = *(const float4*)(x + ((size_t)r * 512 + t) * 512 + k0 + c4);
            As[r][c4 + 0] = f2tf(v.x);
            As[r][c4 + 1] = f2tf(v.y);
            As[r][c4 + 2] = f2tf(v.z);
            As[r][c4 + 3] = f2tf(v.w);
        }
        #pragma unroll
        for (int it = 0; it < 2; it++) {
            int i  = tid + it * 256;
            int r  = i >> 2;
            int c4 = (i & 3) * 4;
            float4 v = *(const float4*)(Wih + (size_t)(n0 + r) * 512 + k0 + c4);
            Bs[r][c4 + 0] = f2tf(v.x);
            Bs[r][c4 + 1] = f2tf(v.y);
            Bs[r][c4 + 2] = f2tf(v.z);
            Bs[r][c4 + 3] = f2tf(v.w);
        }
        __syncthreads();

        #pragma unroll
        for (int ks = 0; ks < 2; ks++) {
            const int kb = ks * 8;
            unsigned a[4][4];
            #pragma unroll
            for (int mt = 0; mt < 4; mt++) {
                int r = mrow + mt * 16 + gid;
                a[mt][0] = As[r][kb + tig];
                a[mt][1] = As[r + 8][kb + tig];
                a[mt][2] = As[r][kb + tig + 4];
                a[mt][3] = As[r + 8][kb + tig + 4];
            }
            #pragma unroll
            for (int nt = 0; nt < 4; nt++) {
                int n = ncol + nt * 8 + gid;
                unsigned b0 = Bs[n][kb + tig];
                unsigned b1 = Bs[n][kb + tig + 4];
                #pragma unroll
                for (int mt = 0; mt < 4; mt++)
                    mma8(acc[mt][nt], a[mt][0], a[mt][1], a[mt][2], a[mt][3], b0, b1);
            }
        }
        __syncthreads();
    }

    #pragma unroll
    for (int mt = 0; mt < 4; mt++) {
        #pragma unroll
        for (int nt = 0; nt < 4; nt++) {
            int r0 = mrow + mt * 16 + gid;
            int c0 = n0 + ncol + nt * 8 + 2 * tig;
            float bv0 = __ldg(bias + c0);
            float bv1 = __ldg(bias + c0 + 1);
            size_t base0 = ((size_t)t * 128 + r0) * 1536 + c0;
            size_t base1 = ((size_t)t * 128 + r0 + 8) * 1536 + c0;
            *(float2*)&g_ig[base0] = make_float2(acc[mt][nt][0] + bv0, acc[mt][nt][1] + bv1);
            *(float2*)&g_ig[base1] = make_float2(acc[mt][nt][2] + bv0, acc[mt][nt][3] + bv1);
        }
    }
}

// ===========================================================================
// Kernel 2: persistent GRU recurrence — EXACT round-5 structure (measured
//   ~1.75ms) + step-parity g_h double buffer for provable safety.
//   grid 128 (4 row-groups x 32 col-groups), 256 thr (8 warps = K-groups).
// ===========================================================================
#define WS_PITCH 516
#define SG_PITCH 52
#define SMEM_K2_BYTES (80 * WS_PITCH * 4)   // Ws+Hs; Sg aliases Ws

__global__ void __launch_bounds__(256, 1) k_rec(const float* __restrict__ Whh,
                                                const float* __restrict__ bn) {
    extern __shared__ unsigned smem[];
    unsigned* Ws = smem;                     // [48][516] init only
    unsigned* Hs = smem + 48 * WS_PITCH;     // [32][516] tf32 h tile
    float*    Sg = (float*)smem;             // [8][32][52] (aliases Ws)

    const int tid  = threadIdx.x;
    const int lane = tid & 31;
    const int w    = tid >> 5;
    const int gid  = lane >> 2;
    const int tig  = lane & 3;
    const int mg   = blockIdx.x >> 5;
    const int cg   = blockIdx.x & 31;
    const int rowbase = mg * 32;
    const int colbase = cg * 16;

    for (int i = tid; i < 48 * 128; i += 256) {
        int lr   = i >> 7;
        int c4   = (i & 127) * 4;
        int grow = (lr >> 4) * 512 + colbase + (lr & 15);
        float4 v = *(const float4*)(Whh + (size_t)grow * 512 + c4);
        uint4 u = make_uint4(f2tf(v.x), f2tf(v.y), f2tf(v.z), f2tf(v.w));
        *(uint4*)&Ws[lr * WS_PITCH + c4] = u;
    }
    for (int i = tid; i < 32 * WS_PITCH; i += 256) Hs[i] = 0u;
    __syncthreads();

    const int kbase = w * 64;
    unsigned wf[8][6][2];
    #pragma unroll
    for (int kt = 0; kt < 8; kt++)
        #pragma unroll
        for (int nt = 0; nt < 6; nt++) {
            int base = (nt * 8 + gid) * WS_PITCH + kbase + kt * 8 + tig;
            wf[kt][nt][0] = Ws[base];
            wf[kt][nt][1] = Ws[base + 4];
        }
    __syncthreads();   // Ws free -> Sg

    const int bb = tid >> 3;
    const int jj = (tid * 2) & 15;
    const float bn0 = __ldg(bn + colbase + jj);
    const float bn1 = __ldg(bn + colbase + jj + 1);
    float2 hp = make_float2(0.0f, 0.0f);

    float* Sgw = Sg + w * 32 * SG_PITCH;
    unsigned long long* myflag = &g_flag[(mg * 32 + cg) * 16];
    const unsigned long long* pf = &g_flag[(mg * 32 + w * 4 + (lane & 3)) * 16];
    const int rs_half = lane >> 4;
    const int rs_c4   = (lane & 15) * 4;

    for (int t = 0; t < T_; t++) {
        const float* igb = g_ig + ((size_t)t * 128 + rowbase + bb) * 1536 + colbase + jj;
        float2 igr = __ldg((const float2*)(igb));
        float2 igz = __ldg((const float2*)(igb + 512));
        float2 ign = __ldg((const float2*)(igb + 1024));

        if (t > 0) {
            // Parallel wait: lanes 0..3 each poll one of this warp's 4 producers
            if (lane < 4) {
                while (ld_acquire(pf) < (unsigned long long)t) { }
            }
            __syncwarp();
            // Full restage of own K slice from parity buffer (t-1)&1
            const unsigned* hsrc = g_h + (size_t)((t - 1) & 1) * HB_;
            #pragma unroll
            for (int rr = 0; rr < 16; rr++) {
                int row = rr * 2 + rs_half;
                const uint4* src = (const uint4*)(hsrc + (rowbase + row) * 512 + kbase + rs_c4);
                uint4 v;
                asm volatile("ld.global.cg.v4.u32 {%0,%1,%2,%3}, [%4];"
                             : "=r"(v.x), "=r"(v.y), "=r"(v.z), "=r"(v.w) : "l"(src));
                *(uint4*)&Hs[row * WS_PITCH + kbase + rs_c4] = v;
            }
        }

        float c[2][6][4];
        #pragma unroll
        for (int m = 0; m < 2; m++)
            #pragma unroll
            for (int n = 0; n < 6; n++)
                #pragma unroll
                for (int q = 0; q < 4; q++) c[m][n][q] = 0.0f;

        #pragma unroll
        for (int kt = 0; kt < 8; kt++) {
            const int kb = kbase + kt * 8;
            unsigned a[2][4];
            #pragma unroll
            for (int m = 0; m < 2; m++) {
                int r = m * 16 + gid;
                a[m][0] = Hs[r * WS_PITCH + kb + tig];
                a[m][1] = Hs[(r + 8) * WS_PITCH + kb + tig];
                a[m][2] = Hs[r * WS_PITCH + kb + tig + 4];
                a[m][3] = Hs[(r + 8) * WS_PITCH + kb + tig + 4];
            }
            #pragma unroll
            for (int n = 0; n < 6; n++) {
                mma8(c[0][n], a[0][0], a[0][1], a[0][2], a[0][3], wf[kt][n][0], wf[kt][n][1]);
                mma8(c[1][n], a[1][0], a[1][1], a[1][2], a[1][3], wf[kt][n][0], wf[kt][n][1]);
            }
        }

        #pragma unroll
        for (int m = 0; m < 2; m++) {
            int r0 = m * 16 + gid, r1 = r0 + 8;
            #pragma unroll
            for (int n = 0; n < 6; n++) {
                int cb = n * 8 + 2 * tig;
                *(float2*)&Sgw[r0 * SG_PITCH + cb] = make_float2(c[m][n][0], c[m][n][1]);
                *(float2*)&Sgw[r1 * SG_PITCH + cb] = make_float2(c[m][n][2], c[m][n][3]);
            }
        }
        __syncthreads();

        {
            float hr0 = 0.f, hr1 = 0.f, hz0 = 0.f, hz1 = 0.f, hn0 = 0.f, hn1 = 0.f;
            #pragma unroll
            for (int k = 0; k < 8; k++) {
                const float* s = Sg + k * 32 * SG_PITCH + bb * SG_PITCH;
                float2 vr = *(const float2*)(s + jj);
                float2 vz = *(const float2*)(s + 16 + jj);
                float2 vn = *(const float2*)(s + 32 + jj);
                hr0 += vr.x; hr1 += vr.y;
                hz0 += vz.x; hz1 += vz.y;
                hn0 += vn.x; hn1 += vn.y;
            }
            float r0 = sigf(igr.x + hr0);
            float r1 = sigf(igr.y + hr1);
            float z0 = sigf(igz.x + hz0);
            float z1 = sigf(igz.y + hz1);
            float n0 = tanhf(ign.x + r0 * (hn0 + bn0));
            float n1 = tanhf(ign.y + r1 * (hn1 + bn1));
            float h0 = (1.0f - z0) * n0 + z0 * hp.x;
            float h1 = (1.0f - z1) * n1 + z1 * hp.y;
            hp = make_float2(h0, h1);

            if (t < T_ - 1) {
                uint2 uv = make_uint2(f2tf(h0), f2tf(h1));
                unsigned* dst = g_h + (size_t)(t & 1) * HB_
                                + (rowbase + bb) * 512 + colbase + jj;
                asm volatile("st.global.cg.v2.u32 [%0], {%1,%2};"
                             :: "l"(dst), "r"(uv.x), "r"(uv.y) : "memory");
            } else {
                *(float2*)(g_hx + (rowbase + bb) * 512 + colbase + jj) =
                    make_float2(h0, h1);
            }
        }

        if (t == T_ - 1) break;
        __syncthreads();                     // all h stores issued
        if (tid == 0) arrive_release(myflag);   // flag value becomes t+1
    }
}

// ===========================================================================
// Kernel 3: out = h_final @ Wlin^T + blin; warp-per-(b,32n), coalesced.
// ===========================================================================
__global__ void __launch_bounds__(256) k_out(const float* __restrict__ Wlin,
                                             const float* __restrict__ blin,
                                             float* __restrict__ out) {
    const int wg   = blockIdx.x * 8 + (threadIdx.x >> 5);
    const int lane = threadIdx.x & 31;
    const int b    = wg >> 4;
    const int nb   = (wg & 15) * 32;

    float4 h4[4];
    #pragma unroll
    for (int q = 0; q < 4; q++)
        h4[q] = *(const float4*)(g_hx + b * 512 + q * 128 + lane * 4);

    #pragma unroll 4
    for (int i = 0; i < 32; i++) {
        int n = nb + i;
        const float* wr = Wlin + (size_t)n * 512;
        float s = 0.0f;
        #pragma unroll
        for (int q = 0; q < 4; q++) {
            float4 wv = __ldg((const float4*)(wr + q * 128 + lane * 4));
            s += h4[q].x * wv.x + h4[q].y * wv.y + h4[q].z * wv.z + h4[q].w * wv.w;
        }
        s += __shfl_xor_sync(0xFFFFFFFF, s, 16);
        s += __shfl_xor_sync(0xFFFFFFFF, s, 8);
        s += __shfl_xor_sync(0xFFFFFFFF, s, 4);
        s += __shfl_xor_sync(0xFFFFFFFF, s, 2);
        s += __shfl_xor_sync(0xFFFFFFFF, s, 1);
        if (lane == 0) {
            float v = s + __ldg(blin + n);
            if (n < L_) out[b * L_ + n] = v;
            else        out[(size_t)B_ * L_ + b * L_ + (n - L_)] = v;
        }
    }
}

// ===========================================================================
extern "C" void kernel_launch(void* const* d_in, const int* in_sizes, int n_in,
                              void* d_out, int out_size) {
    const float* x    = (const float*)d_in[0];
    const float* Wih  = (const float*)d_in[1];
    const float* Whh  = (const float*)d_in[2];
    const float* b    = (const float*)d_in[3];
    const float* bn   = (const float*)d_in[4];
    const float* Wlin = (const float*)d_in[5];
    const float* blin = (const float*)d_in[6];
    float* out = (float*)d_out;

    cudaFuncSetAttribute(k_rec, cudaFuncAttributeMaxDynamicSharedMemorySize,
                         SMEM_K2_BYTES);

    dim3 g1(12, 512);
    k_igemm<<<g1, 256>>>(x, Wih, b);
    k_zero<<<1, 256>>>();
    k_rec<<<128, 256, SMEM_K2_BYTES>>>(Whh, bn);
    k_out<<<256, 256>>>(Wlin, blin, out);
}